// round 2
// baseline (speedup 1.0000x reference)
#include <cuda_runtime.h>

// SrbQpCtrl: reference collapses to tau = 0 for every batch element.
//   Q = I, q = 0  =>  lambda* = max(0, -q/diag(Q)) = 0 ; tau = broadcast = zeros.
// Output: 2,000,000 x 10 float32 zeros = 80 MB constant fill.
// Strategy: full-chip SIMT STG.E.128 fill to saturate the DRAM write roof
// (memset node measured 5.39 TB/s; target ~6.5-7 TB/s).

__global__ void __launch_bounds__(256) zero_fill_v4(float4* __restrict__ out, int n4) {
    int i = blockIdx.x * blockDim.x + threadIdx.x;
    int stride = gridDim.x * blockDim.x;
    const float4 z = make_float4(0.f, 0.f, 0.f, 0.f);
    #pragma unroll 4
    for (; i < n4; i += stride)
        out[i] = z;
}

extern "C" void kernel_launch(void* const* d_in, const int* in_sizes, int n_in,
                              void* d_out, int out_size) {
    (void)d_in; (void)in_sizes; (void)n_in;
    // out_size = 20,000,000 floats, divisible by 4 -> 5,000,000 float4 stores.
    int n4 = out_size / 4;
    const int threads = 256;
    const int blocks = 148 * 16;  // 2368 blocks: 16/SM, one full wave
    zero_fill_v4<<<blocks, threads>>>((float4*)d_out, n4);

    // Handle any tail elements if out_size is not a multiple of 4 (defensive;
    // 20M is a multiple of 4 so this is a no-op memset of 0 bytes).
    int tail = out_size - n4 * 4;
    if (tail > 0)
        cudaMemsetAsync((float*)d_out + n4 * 4, 0, (size_t)tail * sizeof(float), 0);
}